// round 12
// baseline (speedup 1.0000x reference)
#include <cuda_runtime.h>
#include <cstdint>

#define T_STEPS 1000
#define BATCH   2048
#define FEAT    40
#define H1      8
#define H2      6
#define G1      32

#define CT      10
#define NCHUNK  (T_STEPS / CT)      // 100
#define SITES   (CT * FEAT / 4)     // 100 float4 per chunk
#define EPB     2                   // elements per block

typedef unsigned long long u64;

// ---------------- helpers ----------------
__device__ __forceinline__ u64 pack2(float x, float y) {
    u64 r; asm("mov.b64 %0, {%1, %2};" : "=l"(r) : "f"(x), "f"(y)); return r;
}
__device__ __forceinline__ void unpack2(u64 v, float& x, float& y) {
    asm("mov.b64 {%0, %1}, %2;" : "=f"(x), "=f"(y) : "l"(v));
}
__device__ __forceinline__ u64 fma2(u64 a, u64 b, u64 c) {
    u64 d; asm("fma.rn.f32x2 %0, %1, %2, %3;" : "=l"(d) : "l"(a), "l"(b), "l"(c)); return d;
}
__device__ __forceinline__ u64 mul2(u64 a, u64 b) {
    u64 d; asm("mul.rn.f32x2 %0, %1, %2;" : "=l"(d) : "l"(a), "l"(b)); return d;
}
__device__ __forceinline__ u64 add2(u64 a, u64 b) {
    u64 d; asm("add.rn.f32x2 %0, %1, %2;" : "=l"(d) : "l"(a), "l"(b)); return d;
}
__device__ __forceinline__ u64 scale2(u64 v, float s) {
    float a, b; unpack2(v, a, b); return pack2(a * s, b * s);
}
__device__ __forceinline__ float hadd2(u64 v) {
    float a, b; unpack2(v, a, b); return a + b;
}
__device__ __forceinline__ float tanha(float x) {
    float r; asm("tanh.approx.f32 %0, %1;" : "=f"(r) : "f"(x)); return r;
}
__device__ __forceinline__ float shflf(float v, int src) {
    return __shfl_sync(0xffffffffu, v, src & 31);
}
__device__ __forceinline__ float shflx(float v, int m) {
    return __shfl_xor_sync(0xffffffffu, v, m);
}
__device__ __forceinline__ uint32_t smem_u32(const void* p) {
    uint32_t a;
    asm("{ .reg .u64 t; cvta.to.shared.u64 t, %1; cvt.u32.u64 %0, t; }" : "=r"(a) : "l"(p));
    return a;
}
__device__ __forceinline__ void cp_async16(uint32_t saddr, const void* gaddr) {
    asm volatile("cp.async.cg.shared.global [%0], [%1], 16;" :: "r"(saddr), "l"(gaddr));
}
__device__ __forceinline__ void cp_commit() {
    asm volatile("cp.async.commit_group;" ::: "memory");
}
template <int N>
__device__ __forceinline__ void cp_wait() {
    asm volatile("cp.async.wait_group %0;" :: "n"(N) : "memory");
}
#define BAR96() asm volatile("bar.sync 0, 96;" ::: "memory")

// ============================================================================
// consumer step (R10 proven, verbatim): layer1(i) + layer2(i-1), XOR gathers.
// slab shs[2][24]: [0..7]=h1, [8..15]=x2, [16..21]=h2
// L1 gates at lanes: i 0-7 | f 8-15 | g 16-23 | o 24-31  (c1 on lanes 8-15)
// L2 gates at lanes: i 0-5 | f 8-13 | g 16-21 | o 24-29  (c2 on lanes 8-13)
// ============================================================================
template <int RD>
__device__ __forceinline__ void rec_step(
    float en, int lane, float gval,
    float (*shs)[24],
    const u64* __restrict__ w1p, const u64* __restrict__ wi2p,
    const u64* __restrict__ wh2p, u64 bias2p,
    float cn1, float ca1, float cn2, float ca2,
    float& c1, float& c2)
{
    constexpr int WR = RD ^ 1;

    const ulonglong2* hp = reinterpret_cast<const ulonglong2*>(&shs[RD][0]);
    ulonglong2 h01 = hp[0], h23 = hp[1];   // h1[0..7]
    ulonglong2 x01 = hp[2], x23 = hp[3];   // x2[0..7]
    ulonglong2 h2a = hp[4];                // h2[0..3]
    u64        h2b = reinterpret_cast<const u64*>(&shs[RD][0])[10];  // h2[4..5]

    // layer1: g1 = gval + h1 . w1
    u64 C = mul2(h01.x, w1p[0]);
    C = fma2(h01.y, w1p[1], C);
    u64 D = mul2(h23.x, w1p[2]);
    D = fma2(h23.y, w1p[3], D);
    float g1 = gval + hadd2(add2(C, D));

    // layer2: g2 = bias2 + x2 . wi2 + h2 . wh2
    u64 P = fma2(x01.x, wi2p[0], bias2p);
    u64 Q = mul2(x01.y, wi2p[1]);
    P = fma2(x23.x, wi2p[2], P);
    Q = fma2(x23.y, wi2p[3], Q);
    P = fma2(h2a.x, wh2p[0], P);
    Q = fma2(h2a.y, wh2p[1], Q);
    P = fma2(h2b,   wh2p[2], P);
    float g2 = hadd2(add2(P, Q));

    float a1 = fmaf(cn1, tanha(g1), ca1);
    float a2 = fmaf(cn2, tanha(g2), ca2);

    // XOR gathers
    float s1 = shflx(a1, 16);
    float s2 = shflx(a2, 16);
    float p1 = a1 * s1;
    float p2 = a2 * s2;
    float t1 = shflx(p1, 8);     // lanes 8-15 <- i*g (L1)
    float t2 = shflx(p2, 8);     // lanes 8-13 <- i*g (L2)

    // state owners: lanes 8-15 hold a1=f, s1=o
    c1 = fmaf(a1, c1, t1);
    float h1v = s1 * tanha(c1);
    float x2v = tanha(h1v);

    // lanes 8-13 hold a2=f2, s2=o2
    c2 = en * fmaf(a2, c2, t2);
    float h2v = s2 * tanha(c2);

    if (lane >= 8 && lane < 16) {
        shs[WR][lane - 8] = h1v;   // h1 slot
        shs[WR][lane]     = x2v;   // x2 slot
    }
    if (lane >= 8 && lane < 14) shs[WR][8 + lane] = h2v;   // h2 slot 16+(lane-8)
    __syncwarp();
}

// producer gate compute for one element, one chunk (R10 verbatim inner loop)
__device__ __forceinline__ void produce_chunk(
    const float (*src)[FEAT], float (*dstg)[16][2],
    int l, int h,
    const u64* __restrict__ wA, const u64* __restrict__ wB,
    float bA, float bB)
{
#pragma unroll
    for (int p = 0; p < 5; p++) {
        int r = 2 * p + h;
        const ulonglong2* xr = reinterpret_cast<const ulonglong2*>(&src[r][0]);
        u64 a0 = pack2(bA, 0.f), a1 = 0ull;
        u64 b0 = pack2(bB, 0.f), b1 = 0ull;
#pragma unroll
        for (int q = 0; q < FEAT / 4; q++) {
            ulonglong2 v = xr[q];
            a0 = fma2(wA[2 * q],     v.x, a0);
            a1 = fma2(wA[2 * q + 1], v.y, a1);
            b0 = fma2(wB[2 * q],     v.x, b0);
            b1 = fma2(wB[2 * q + 1], v.y, b1);
        }
        *reinterpret_cast<u64*>(&dstg[r][l][0]) =
            pack2(hadd2(add2(a0, a1)), hadd2(add2(b0, b1)));
    }
}

// ============================================================================
// fused kernel: 1 block = 2 batch elements, 3 warps
// warp 0,1: consumers (element = wid). warp 2: producer serving both.
// ============================================================================
__global__ void __launch_bounds__(96)
fused_pc(const float* __restrict__ x,
         const float* __restrict__ W_ih1,
         const float* __restrict__ W_hh1,
         const float* __restrict__ b_ih1,
         const float* __restrict__ b_hh1,
         const float* __restrict__ W_ih2,
         const float* __restrict__ W_hh2,
         const float* __restrict__ b_ih2,
         const float* __restrict__ b_hh2,
         const float* __restrict__ W_fc,
         const float* __restrict__ b_fc,
         float* __restrict__ out) {
    __shared__ __align__(16) float sgate[EPB][2][CT][16][2];  // packed gate rings
    __shared__ __align__(16) float sx[EPB][2][CT][FEAT];      // x staging (cp.async)
    __shared__ __align__(16) float shs[EPB][2][24];           // hidden slabs

    int tid  = threadIdx.x;
    int lane = tid & 31;
    int wid  = tid >> 5;

    if (wid == EPB) {
        // ======================= PRODUCER (serves EPB elements) ==============
        int l = lane & 15, h = lane >> 4;
        int gA = l, gB = l + 16;
        float cmA = 0.5f;
        float cmB = (l < 8) ? 1.0f : 0.5f;

        u64 wA[FEAT / 2], wB[FEAT / 2];
        {
            const u64* wra = reinterpret_cast<const u64*>(W_ih1 + gA * FEAT);
            const u64* wrb = reinterpret_cast<const u64*>(W_ih1 + gB * FEAT);
#pragma unroll
            for (int p = 0; p < FEAT / 2; p++) {
                wA[p] = scale2(wra[p], cmA);
                wB[p] = scale2(wrb[p], cmB);
            }
        }
        float bA = cmA * (b_ih1[gA] + b_hh1[gA]);
        float bB = cmB * (b_ih1[gB] + b_hh1[gB]);

        const float4* xb[EPB];
        uint32_t sxa[EPB][2];
#pragma unroll
        for (int e = 0; e < EPB; e++) {
            xb[e] = reinterpret_cast<const float4*>(
                        x + (size_t)(blockIdx.x * EPB + e) * T_STEPS * FEAT);
            sxa[e][0] = smem_u32(&sx[e][0][0][0]);
            sxa[e][1] = smem_u32(&sx[e][1][0][0]);
        }

        // issue chunks 0,1 for both elements (one commit group per chunk)
#pragma unroll
        for (int e = 0; e < EPB; e++)
#pragma unroll
            for (int i = 0; i < 4; i++) {
                int s = lane + 32 * i;
                if (s < SITES) cp_async16(sxa[e][0] + 16 * s, xb[e] + s);
            }
        cp_commit();
#pragma unroll
        for (int e = 0; e < EPB; e++)
#pragma unroll
            for (int i = 0; i < 4; i++) {
                int s = lane + 32 * i;
                if (s < SITES) cp_async16(sxa[e][1] + 16 * s, xb[e] + SITES + s);
            }
        cp_commit();
        cp_wait<1>();
        __syncwarp();

#pragma unroll
        for (int e = 0; e < EPB; e++)
            produce_chunk(sx[e][0], sgate[e][0], l, h, wA, wB, bA, bB);
        BAR96();

#pragma unroll 1
        for (int c = 0; c < NCHUNK; c++) {
            if (c + 1 < NCHUNK) {
                int c2i = (c + 2 < NCHUNK) ? c + 2 : NCHUNK - 1;
#pragma unroll
                for (int e = 0; e < EPB; e++) {
                    uint32_t dst = sxa[e][c & 1];
#pragma unroll
                    for (int i = 0; i < 4; i++) {
                        int s = lane + 32 * i;
                        if (s < SITES) cp_async16(dst + 16 * s, xb[e] + (size_t)c2i * SITES + s);
                    }
                }
                cp_commit();
                cp_wait<1>();      // chunk c+1 resident (both elements)
                __syncwarp();

#pragma unroll
                for (int e = 0; e < EPB; e++)
                    produce_chunk(sx[e][(c + 1) & 1], sgate[e][(c + 1) & 1],
                                  l, h, wA, wB, bA, bB);
            }
            BAR96();
        }
        cp_wait<0>();
    } else {
        // ======================= CONSUMER (element = wid) =====================
        int b = blockIdx.x * EPB + wid;
        float (*myshs)[24] = shs[wid];

        bool t1c = ((lane >> 3) == 2);
        float cm1 = t1c ? 1.f : 0.5f, cn1 = t1c ? 1.f : 0.5f, ca1 = t1c ? 0.f : 0.5f;
        bool v2 = ((lane & 7) < 6) && (lane < 30);
        int g2i = lane - 2 * (lane >> 3);
        bool t2c = (lane >= 16 && lane < 22);
        float cm2 = t2c ? 1.f : 0.5f, cn2 = t2c ? 1.f : 0.5f, ca2 = t2c ? 0.f : 0.5f;

        u64 w1p[H1 / 2];
#pragma unroll
        for (int j = 0; j < H1 / 2; j++)
            w1p[j] = pack2(cm1 * W_hh1[lane * H1 + 2 * j], cm1 * W_hh1[lane * H1 + 2 * j + 1]);

        u64 wi2p[H1 / 2], wh2p[H2 / 2], bias2p = 0ull;
#pragma unroll
        for (int j = 0; j < H1 / 2; j++) wi2p[j] = 0ull;
#pragma unroll
        for (int j = 0; j < H2 / 2; j++) wh2p[j] = 0ull;
        if (v2) {
#pragma unroll
            for (int j = 0; j < H1 / 2; j++)
                wi2p[j] = pack2(cm2 * W_ih2[g2i * H1 + 2 * j], cm2 * W_ih2[g2i * H1 + 2 * j + 1]);
#pragma unroll
            for (int j = 0; j < H2 / 2; j++)
                wh2p[j] = pack2(cm2 * W_hh2[g2i * H2 + 2 * j], cm2 * W_hh2[g2i * H2 + 2 * j + 1]);
            bias2p = pack2(cm2 * (b_ih2[g2i] + b_hh2[g2i]), 0.f);
        }

        if (lane < 24) myshs[1][lane] = 0.f;
        float c1 = 0.f, c2 = 0.f;
        BAR96();

        int gidx = (lane & 15) * 2 + (lane >> 4);   // packed-ring offset

#pragma unroll 1
        for (int c = 0; c < NCHUNK; c++) {
            const float* gr = &sgate[wid][c & 1][0][0][0];
            float en0 = (c == 0) ? 0.f : 1.f;

            rec_step<1>(en0, lane, gr[0 * 32 + gidx], myshs, w1p, wi2p, wh2p, bias2p,
                        cn1, ca1, cn2, ca2, c1, c2);
            rec_step<0>(1.f, lane, gr[1 * 32 + gidx], myshs, w1p, wi2p, wh2p, bias2p,
                        cn1, ca1, cn2, ca2, c1, c2);
            rec_step<1>(1.f, lane, gr[2 * 32 + gidx], myshs, w1p, wi2p, wh2p, bias2p,
                        cn1, ca1, cn2, ca2, c1, c2);
            rec_step<0>(1.f, lane, gr[3 * 32 + gidx], myshs, w1p, wi2p, wh2p, bias2p,
                        cn1, ca1, cn2, ca2, c1, c2);
            rec_step<1>(1.f, lane, gr[4 * 32 + gidx], myshs, w1p, wi2p, wh2p, bias2p,
                        cn1, ca1, cn2, ca2, c1, c2);
            rec_step<0>(1.f, lane, gr[5 * 32 + gidx], myshs, w1p, wi2p, wh2p, bias2p,
                        cn1, ca1, cn2, ca2, c1, c2);
            rec_step<1>(1.f, lane, gr[6 * 32 + gidx], myshs, w1p, wi2p, wh2p, bias2p,
                        cn1, ca1, cn2, ca2, c1, c2);
            rec_step<0>(1.f, lane, gr[7 * 32 + gidx], myshs, w1p, wi2p, wh2p, bias2p,
                        cn1, ca1, cn2, ca2, c1, c2);
            rec_step<1>(1.f, lane, gr[8 * 32 + gidx], myshs, w1p, wi2p, wh2p, bias2p,
                        cn1, ca1, cn2, ca2, c1, c2);
            rec_step<0>(1.f, lane, gr[9 * 32 + gidx], myshs, w1p, wi2p, wh2p, bias2p,
                        cn1, ca1, cn2, ca2, c1, c2);
            BAR96();
        }

        // ---- epilogue: layer2(999) from myshs[1] (x2(999), h2(998)) ----
        const ulonglong2* hp = reinterpret_cast<const ulonglong2*>(&myshs[1][0]);
        ulonglong2 x01 = hp[2], x23 = hp[3], h2a = hp[4];
        u64 h2b = reinterpret_cast<const u64*>(&myshs[1][0])[10];

        u64 P = fma2(x01.x, wi2p[0], bias2p);
        u64 Q = mul2(x01.y, wi2p[1]);
        P = fma2(x23.x, wi2p[2], P);
        Q = fma2(x23.y, wi2p[3], Q);
        P = fma2(h2a.x, wh2p[0], P);
        Q = fma2(h2a.y, wh2p[1], Q);
        P = fma2(h2b,   wh2p[2], P);
        float g2 = hadd2(add2(P, Q));

        float a2 = fmaf(cn2, tanha(g2), ca2);
        float s2 = shflx(a2, 16);
        float p2 = a2 * s2;
        float t2 = shflx(p2, 8);
        c2 = fmaf(a2, c2, t2);                 // lanes 8-13
        float tx = tanha(s2 * tanha(c2));      // tanh(h2(999)) at lanes 8-13

        float s = b_fc[0];
#pragma unroll
        for (int j = 0; j < H2; j++)
            s = fmaf(shflf(tx, 8 + j), W_fc[j], s);
        if (lane == 0)
            out[b] = fmaf(0.5f, tanha(0.5f * s), 0.5f);
    }
}

// ============================================================================
extern "C" void kernel_launch(void* const* d_in, const int* in_sizes, int n_in,
                              void* d_out, int out_size) {
    const float* x     = (const float*)d_in[0];
    const float* W_ih1 = (const float*)d_in[1];
    const float* W_hh1 = (const float*)d_in[2];
    const float* b_ih1 = (const float*)d_in[3];
    const float* b_hh1 = (const float*)d_in[4];
    const float* W_ih2 = (const float*)d_in[5];
    const float* W_hh2 = (const float*)d_in[6];
    const float* b_ih2 = (const float*)d_in[7];
    const float* b_hh2 = (const float*)d_in[8];
    const float* W_fc  = (const float*)d_in[9];
    const float* b_fc  = (const float*)d_in[10];
    float* out = (float*)d_out;

    fused_pc<<<BATCH / EPB, 96>>>(x, W_ih1, W_hh1, b_ih1, b_hh1,
                                  W_ih2, W_hh2, b_ih2, b_hh2, W_fc, b_fc, out);
}